// round 10
// baseline (speedup 1.0000x reference)
#include <cuda_runtime.h>
#include <stdint.h>

#define BATCH 16
#define CIN   64
#define CF    64
#define FH    45
#define FW    80
#define NANCH 2784
#define KOUT  75
#define KPAD  80    // padded K (cols 75..79 are zero)
#define OUTW  77

#define NBLK  148
#define NTHR  512

typedef unsigned long long ull;

// ---------------------------------------------------------------------------
// Scratch (static __device__ — allocation-free)
// ---------------------------------------------------------------------------
__device__ float g_W2[FH * CIN * KPAD];          // [y][cin][k]
__device__ float g_cb[FH * KPAD];                // [y][k]
__device__ float g_A[BATCH * FH * FW * KPAD];    // [b][y][x][k]

// Grid barrier state (monotonic generation; count wraps via atomicInc)
__device__ unsigned g_bar_count = 0;
__device__ unsigned g_bar_gen   = 0;

__device__ __forceinline__ void grid_sync() {
    __syncthreads();
    if (threadIdx.x == 0) {
        __threadfence();
        unsigned my = *((volatile unsigned*)&g_bar_gen);
        if (atomicInc(&g_bar_count, NBLK - 1) == NBLK - 1) {
            atomicAdd(&g_bar_gen, 1);        // release
        } else {
            while (*((volatile unsigned*)&g_bar_gen) == my) __nanosleep(64);
        }
        __threadfence();
    }
    __syncthreads();
}

// ---------------------------------------------------------------------------
// f32x2 packed-math helpers (sm_103a)
// ---------------------------------------------------------------------------
__device__ __forceinline__ ull ffma2(ull a, ull b, ull c) {
    ull d;
    asm("fma.rn.f32x2 %0, %1, %2, %3;" : "=l"(d) : "l"(a), "l"(b), "l"(c));
    return d;
}
__device__ __forceinline__ ull add2(ull a, ull b) {
    ull r;
    asm("add.rn.f32x2 %0, %1, %2;" : "=l"(r) : "l"(a), "l"(b));
    return r;
}
__device__ __forceinline__ ull pk2(float x) {
    ull r;
    asm("mov.b64 %0, {%1, %1};" : "=l"(r) : "f"(x));
    return r;
}
__device__ __forceinline__ void cpa16(uint32_t s, const void* g) {
    asm volatile("cp.async.ca.shared.global [%0], [%1], 16;" :: "r"(s), "l"(g));
}
__device__ __forceinline__ void cpa_commit() {
    asm volatile("cp.async.commit_group;");
}
template <int N>
__device__ __forceinline__ void cpa_wait() {
    asm volatile("cp.async.wait_group %0;" :: "n"(N));
}

// ---------------------------------------------------------------------------
// Fused-kernel smem layout (dynamic, 82944 B):
//  phase1: cw_s  [64*65]f           @ 0      (16640 B)
//  phase2: w_s   [64*80]f           @ 0      (20480 B)
//          cb_s  [80]f              @ 20480
//          xs_s  [3][64*80]f        @ 21504  (61440 B)  -> end 82944
//  phase3: bufs  2 x 81*320 B       @ 0      (51840 B)
//          xs8   [45][384] u8       @ 51840  (17280 B)  -> end 69120
// ---------------------------------------------------------------------------
#define NL       348
#define GRPS     12
#define ACCN     29          // NL / GRPS
#define ROWB     (FW * 4)                 // 320 B per x-row
#define BUFB     ((FW + 1) * ROWB)        // 81 rows = 25920 B
#define XSROW    384
#define SMEM_DYN 82944

__global__ void __launch_bounds__(NTHR, 1) fused_kernel(
    const float* __restrict__ x,
    const float* __restrict__ conv_w, const float* __restrict__ conv_b,
    const float* __restrict__ cls_w,  const float* __restrict__ cls_b,
    const float* __restrict__ reg_w,  const float* __restrict__ reg_b,
    const float* __restrict__ anchors,
    const int*   __restrict__ cut_xs,
    const uint8_t* __restrict__ invalid,
    float*       __restrict__ out)
{
    extern __shared__ __align__(16) char smem[];
    const int t = threadIdx.x;

    // ======================= Phase 1: prep =================================
    {
        float* cw_s = (float*)smem;   // [cf][cinx(65)]
        for (int i = t; i < CF * 65; i += NTHR) {
            int cf = i / 65, cx = i % 65;
            cw_s[i] = (cx < CIN) ? conv_w[cf * CIN + cx] : conv_b[cf];
        }
        __syncthreads();

        const int TOT = FH * 65 * KPAD;   // 234000
        for (int o = blockIdx.x * NTHR + t; o < TOT; o += NBLK * NTHR) {
            int k  = o % KPAD;
            int r  = o / KPAD;
            int cx = r % 65;
            int y  = r / 65;
            float acc = 0.f;
            if (k < 2) {
                const float* w = cls_w + y * 2 + k;
                #pragma unroll 8
                for (int cf = 0; cf < CF; ++cf)
                    acc += cw_s[cf * 65 + cx] * w[cf * (FH * 2)];
            } else if (k < 75) {
                const float* w = reg_w + y * 73 + (k - 2);
                #pragma unroll 8
                for (int cf = 0; cf < CF; ++cf)
                    acc += cw_s[cf * 65 + cx] * w[cf * (FH * 73)];
            }
            if (cx < CIN) g_W2[((size_t)y * CIN + cx) * KPAD + k] = acc;
            else          g_cb[y * KPAD + k] = acc;
        }
    }
    grid_sync();

    // ======================= Phase 2: A-GEMM ===============================
    {
        float* w_s  = (float*)smem;             // [cin][k]
        float* cb_s = (float*)(smem + 20480);
        float* xs_s = (float*)(smem + 21504);   // [g][cin][x]

        for (int item = blockIdx.x; item < FH * 6; item += NBLK) {
            int y = item / 6, btri = item % 6;

            const float4* wsrc = (const float4*)(g_W2 + (size_t)y * CIN * KPAD);
            for (int i = t; i < CIN * KPAD / 4; i += NTHR) ((float4*)w_s)[i] = wsrc[i];
            if (t < KPAD) cb_s[t] = g_cb[y * KPAD + t];
            for (int i = t; i < 3 * CIN * FW / 4; i += NTHR) {
                int g  = i / (CIN * FW / 4);
                int ii = i % (CIN * FW / 4);
                int b  = btri * 3 + g;
                if (b < BATCH) {
                    int cin = ii / 20, x4 = ii % 20;
                    ((float4*)xs_s)[i] =
                        ((const float4*)(x + ((size_t)(b * CIN + cin) * FH + y) * FW))[x4];
                }
            }
            __syncthreads();

            int g = t / 160, gt = t % 160;
            int b = btri * 3 + g;
            if (g < 3 && b < BATCH) {
                int xg = gt / 10, kg = gt % 10;
                int x0 = xg * 5, k0 = kg * 8;
                const float* xs_g = xs_s + g * (CIN * FW);

                ull acc[5][4];
                {
                    ulonglong2 c01 = *(const ulonglong2*)&cb_s[k0];
                    ulonglong2 c23 = *(const ulonglong2*)&cb_s[k0 + 4];
                    #pragma unroll
                    for (int i = 0; i < 5; ++i) {
                        acc[i][0] = c01.x; acc[i][1] = c01.y;
                        acc[i][2] = c23.x; acc[i][3] = c23.y;
                    }
                }
                #pragma unroll 4
                for (int cin = 0; cin < CIN; ++cin) {
                    ulonglong2 wA = *(const ulonglong2*)&w_s[cin * KPAD + k0];
                    ulonglong2 wB = *(const ulonglong2*)&w_s[cin * KPAD + k0 + 4];
                    float xv[5];
                    #pragma unroll
                    for (int i = 0; i < 5; ++i) xv[i] = xs_g[cin * FW + x0 + i];
                    #pragma unroll
                    for (int i = 0; i < 5; ++i) {
                        ull px = pk2(xv[i]);
                        acc[i][0] = ffma2(px, wA.x, acc[i][0]);
                        acc[i][1] = ffma2(px, wA.y, acc[i][1]);
                        acc[i][2] = ffma2(px, wB.x, acc[i][2]);
                        acc[i][3] = ffma2(px, wB.y, acc[i][3]);
                    }
                }
                float* Ab = g_A + ((size_t)(b * FH + y) * FW) * KPAD;
                #pragma unroll
                for (int i = 0; i < 5; ++i) {
                    ulonglong2* dst = (ulonglong2*)(Ab + (x0 + i) * KPAD + k0);
                    dst[0] = make_ulonglong2(acc[i][0], acc[i][1]);
                    dst[1] = make_ulonglong2(acc[i][2], acc[i][3]);
                }
            }
            __syncthreads();   // smem reuse across items
        }
    }
    grid_sync();

    // ======================= Phase 3: gather-reduce ========================
    if (blockIdx.x < 128) {
        char*    bufs = smem;
        uint8_t* xs8  = (uint8_t*)(smem + 2 * BUFB);

        int b  = blockIdx.x >> 3;
        int n0 = (blockIdx.x & 7) * NL;

        for (int i = t; i < 2 * FW; i += NTHR) {
            int buf = i / FW, xx = i % FW;
            ((float*)(bufs + buf * BUFB + FW * ROWB))[xx] = 0.f;   // pad row
        }
        for (int i = t; i < NL * FH; i += NTHR) {
            int nl = i / FH, yy = i % FH;
            int xc = cut_xs[(size_t)(n0 + nl) * FH + yy];
            if (invalid[(size_t)(n0 + nl) * FH + yy]) xc = FW;
            int grp = nl / ACCN, j = nl % ACCN;
            xs8[yy * XSROW + grp * 32 + j] = (uint8_t)xc;
        }

        const char* Ab = (const char*)(g_A + (size_t)b * FH * FW * KPAD);

        {
            uint32_t sdst = (uint32_t)__cvta_generic_to_shared(bufs);
            for (int i = t; i < FW * KPAD / 4; i += NTHR)
                cpa16(sdst + i * 16, Ab + i * 16);
            cpa_commit();
        }

        int grp = t / 38, kp = t % 38;
        bool active = (grp < GRPS);
        uint32_t xsoff = grp * 32;

        ull acc[ACCN];
        #pragma unroll
        for (int j = 0; j < ACCN; ++j) acc[j] = 0;

        #pragma unroll 1
        for (int y = 0; y < FH; ++y) {
            int cur = y & 1;
            __syncthreads();
            if (y + 1 < FH) {
                uint32_t sdst = (uint32_t)__cvta_generic_to_shared(bufs + (1 - cur) * BUFB);
                const char* src = Ab + (size_t)(y + 1) * FW * KPAD * 4;
                for (int i = t; i < FW * KPAD / 4; i += NTHR)
                    cpa16(sdst + i * 16, src + i * 16);
                cpa_commit();
                cpa_wait<1>();
            } else {
                cpa_wait<0>();
            }
            __syncthreads();

            if (active) {
                const char* A_s = bufs + cur * BUFB + kp * 8;
                const uint4* xw = (const uint4*)(xs8 + y * XSROW + xsoff);
                uint4 u0 = xw[0];
                uint4 u1 = xw[1];
                uint32_t uw[8] = {u0.x, u0.y, u0.z, u0.w, u1.x, u1.y, u1.z, u1.w};
                #pragma unroll
                for (int j = 0; j < ACCN; ++j) {
                    uint32_t c = (uw[j >> 2] >> ((j & 3) * 8)) & 0xFFu;
                    ull v = *(const ull*)(A_s + c * ROWB);
                    acc[j] = add2(acc[j], v);
                }
            }
        }

        if (active) {
            int k = 2 * kp;
            float b0 = (kp == 0) ? cls_b[0] : reg_b[k - 2];
            float b1 = (kp == 0) ? cls_b[1] : ((kp < 37) ? reg_b[k - 1] : 0.f);

            #pragma unroll 4
            for (int j = 0; j < ACCN; ++j) {
                int n = n0 + grp * ACCN + j;
                float* o = out + (size_t)(b * NANCH + n) * OUTW;
                const float* an = anchors + (size_t)n * OUTW;
                float lo = __uint_as_float((uint32_t)(acc[j] & 0xFFFFFFFFull));
                float hi = __uint_as_float((uint32_t)(acc[j] >> 32));
                if (kp == 0) {
                    o[0] = lo + b0;
                    o[1] = hi + b1;
                    o[2] = an[2];
                    o[3] = an[3];
                } else if (kp < 37) {
                    o[k + 2] = lo + b0 + an[k + 2];
                    o[k + 3] = hi + b1 + an[k + 3];
                } else {   // kp == 37: k=74 valid, k=75 is padding
                    o[76] = lo + b0 + an[76];
                }
            }
        }
    }
}

// ---------------------------------------------------------------------------
extern "C" void kernel_launch(void* const* d_in, const int* in_sizes, int n_in,
                              void* d_out, int out_size) {
    const float*   x        = (const float*)d_in[0];
    const float*   conv_w   = (const float*)d_in[1];
    const float*   conv_b   = (const float*)d_in[2];
    const float*   cls_w    = (const float*)d_in[3];
    const float*   cls_b    = (const float*)d_in[4];
    const float*   reg_w    = (const float*)d_in[5];
    const float*   reg_b    = (const float*)d_in[6];
    const float*   anchors  = (const float*)d_in[7];
    const int*     cut_xs   = (const int*)d_in[8];
    const uint8_t* invalid  = (const uint8_t*)d_in[9];
    float* out = (float*)d_out;

    // Idempotent, capture-legal.
    cudaFuncSetAttribute(fused_kernel,
                         cudaFuncAttributeMaxDynamicSharedMemorySize, SMEM_DYN);

    fused_kernel<<<NBLK, NTHR, SMEM_DYN>>>(x, conv_w, conv_b, cls_w, cls_b,
                                           reg_w, reg_b, anchors, cut_xs,
                                           invalid, out);
}

// round 13
// speedup vs baseline: 1.0124x; 1.0124x over previous
#include <cuda_runtime.h>
#include <stdint.h>

#define BATCH 16
#define CIN   64
#define CF    64
#define FH    45
#define FW    80
#define NANCH 2784
#define KOUT  75
#define KPAD  80    // padded K (cols 75..79 are zero)
#define OUTW  77

#define NBLK  148
#define NTHR  512

typedef unsigned long long ull;

// ---------------------------------------------------------------------------
// Scratch (static __device__ — allocation-free)
// ---------------------------------------------------------------------------
__device__ float g_W2[FH * CIN * KPAD];          // [y][cin][k]
__device__ float g_cb[FH * KPAD];                // [y][k]
__device__ float g_A[BATCH * FH * FW * KPAD];    // [b][y][x][k]

// Grid barrier state (monotonic generation; count wraps via atomicInc)
__device__ unsigned g_bar_count = 0;
__device__ unsigned g_bar_gen   = 0;

__device__ __forceinline__ void grid_sync() {
    __syncthreads();
    if (threadIdx.x == 0) {
        __threadfence();
        unsigned my = *((volatile unsigned*)&g_bar_gen);
        if (atomicInc(&g_bar_count, NBLK - 1) == NBLK - 1) {
            atomicAdd(&g_bar_gen, 1);        // release
        } else {
            while (*((volatile unsigned*)&g_bar_gen) == my) __nanosleep(64);
        }
        __threadfence();
    }
    __syncthreads();
}

// ---------------------------------------------------------------------------
// f32x2 packed-math helpers (sm_103a)
// ---------------------------------------------------------------------------
__device__ __forceinline__ ull ffma2(ull a, ull b, ull c) {
    ull d;
    asm("fma.rn.f32x2 %0, %1, %2, %3;" : "=l"(d) : "l"(a), "l"(b), "l"(c));
    return d;
}
__device__ __forceinline__ ull add2(ull a, ull b) {
    ull r;
    asm("add.rn.f32x2 %0, %1, %2;" : "=l"(r) : "l"(a), "l"(b));
    return r;
}
__device__ __forceinline__ ull pk2(float x) {
    ull r;
    asm("mov.b64 %0, {%1, %1};" : "=l"(r) : "f"(x));
    return r;
}
__device__ __forceinline__ void cpa16(uint32_t s, const void* g) {
    asm volatile("cp.async.ca.shared.global [%0], [%1], 16;" :: "r"(s), "l"(g));
}
__device__ __forceinline__ void cpa_commit() {
    asm volatile("cp.async.commit_group;");
}
template <int N>
__device__ __forceinline__ void cpa_wait() {
    asm volatile("cp.async.wait_group %0;" :: "n"(N));
}

// ---------------------------------------------------------------------------
// Fused-kernel smem layout (dynamic, 82944 B):
//  phase2: two slabs of 41472 B:
//          w_s [64*80]f @ +0 (20480) | cb_s [80]f @ +20480 | xs_s [64*80]f @ +20800
//  phase3: bufs 2 x 81*320 B @ 0 (51840) | xs8 [45][384] u8 @ 51840 -> 69120
// ---------------------------------------------------------------------------
#define CH       312         // anchors per phase-3 chunk
#define NCH      9           // chunks per batch: 9*312 >= 2784
#define GRPS     12
#define ACCN     26          // CH / GRPS
#define ROWB     (FW * 4)                 // 320 B per x-row
#define BUFB     ((FW + 1) * ROWB)        // 81 rows = 25920 B
#define XSROW    384
#define SLABB    41472
#define SMEM_DYN 82944

__global__ void __launch_bounds__(NTHR, 1) fused_kernel(
    const float* __restrict__ x,
    const float* __restrict__ conv_w, const float* __restrict__ conv_b,
    const float* __restrict__ cls_w,  const float* __restrict__ cls_b,
    const float* __restrict__ reg_w,  const float* __restrict__ reg_b,
    const float* __restrict__ anchors,
    const int*   __restrict__ cut_xs,
    const uint8_t* __restrict__ invalid,
    float*       __restrict__ out)
{
    extern __shared__ __align__(16) char smem[];
    const int t = threadIdx.x;

    // ======================= Phase 1: prep (no smem) ========================
    {
        const int TOT = FH * 65 * KPAD;   // 234000
        for (int o = blockIdx.x * NTHR + t; o < TOT; o += NBLK * NTHR) {
            int k  = o % KPAD;
            int r  = o / KPAD;
            int cx = r % 65;
            int y  = r / 65;
            float acc = 0.f;
            if (k < 75) {
                const float* w;
                int stride;
                if (k < 2) { w = cls_w + y * 2 + k;        stride = FH * 2; }
                else       { w = reg_w + y * 73 + (k - 2); stride = FH * 73; }
                if (cx < CIN) {
                    const float* cw = conv_w + cx;
                    #pragma unroll 8
                    for (int cf = 0; cf < CF; ++cf)
                        acc += __ldg(cw + cf * CIN) * __ldg(w + cf * stride);
                } else {
                    #pragma unroll 8
                    for (int cf = 0; cf < CF; ++cf)
                        acc += __ldg(conv_b + cf) * __ldg(w + cf * stride);
                }
            }
            if (cx < CIN) g_W2[((size_t)y * CIN + cx) * KPAD + k] = acc;
            else          g_cb[y * KPAD + k] = acc;
        }
    }
    grid_sync();

    // ======================= Phase 2: A-GEMM (2 items/block) ===============
    {
        const int sub = t >> 8;        // 0/1: which slab
        const int tt  = t & 255;
        char*  slab = smem + sub * SLABB;
        float* w_s  = (float*)slab;
        float* cb_s = (float*)(slab + 20480);
        float* xs_s = (float*)(slab + 20800);

        for (int base = blockIdx.x * 2; base < FH * BATCH; base += NBLK * 2) {
            int it = base + sub;             // always < 720 (even total)
            int y  = it / BATCH, b = it % BATCH;

            const float4* wsrc = (const float4*)(g_W2 + (size_t)y * CIN * KPAD);
            for (int i = tt; i < CIN * KPAD / 4; i += 256) ((float4*)w_s)[i] = wsrc[i];
            if (tt < KPAD) cb_s[tt] = g_cb[y * KPAD + tt];
            for (int i = tt; i < CIN * FW / 4; i += 256) {
                int cin = i / 20, x4 = i % 20;
                ((float4*)xs_s)[i] =
                    ((const float4*)(x + ((size_t)(b * CIN + cin) * FH + y) * FW))[x4];
            }
            __syncthreads();

            if (tt < 160) {
                int xg = tt / 10, kg = tt % 10;
                int x0 = xg * 5, k0 = kg * 8;

                ull acc[5][4];
                {
                    ulonglong2 c01 = *(const ulonglong2*)&cb_s[k0];
                    ulonglong2 c23 = *(const ulonglong2*)&cb_s[k0 + 4];
                    #pragma unroll
                    for (int i = 0; i < 5; ++i) {
                        acc[i][0] = c01.x; acc[i][1] = c01.y;
                        acc[i][2] = c23.x; acc[i][3] = c23.y;
                    }
                }
                #pragma unroll 4
                for (int cin = 0; cin < CIN; ++cin) {
                    ulonglong2 wA = *(const ulonglong2*)&w_s[cin * KPAD + k0];
                    ulonglong2 wB = *(const ulonglong2*)&w_s[cin * KPAD + k0 + 4];
                    float xv[5];
                    #pragma unroll
                    for (int i = 0; i < 5; ++i) xv[i] = xs_s[cin * FW + x0 + i];
                    #pragma unroll
                    for (int i = 0; i < 5; ++i) {
                        ull px = pk2(xv[i]);
                        acc[i][0] = ffma2(px, wA.x, acc[i][0]);
                        acc[i][1] = ffma2(px, wA.y, acc[i][1]);
                        acc[i][2] = ffma2(px, wB.x, acc[i][2]);
                        acc[i][3] = ffma2(px, wB.y, acc[i][3]);
                    }
                }
                float* Ab = g_A + ((size_t)(b * FH + y) * FW) * KPAD;
                #pragma unroll
                for (int i = 0; i < 5; ++i) {
                    ulonglong2* dst = (ulonglong2*)(Ab + (x0 + i) * KPAD + k0);
                    dst[0] = make_ulonglong2(acc[i][0], acc[i][1]);
                    dst[1] = make_ulonglong2(acc[i][2], acc[i][3]);
                }
            }
            __syncthreads();   // slab reuse across iterations
        }
    }
    grid_sync();

    // ======================= Phase 3: gather-reduce ========================
    if (blockIdx.x < BATCH * NCH) {
        char*    bufs = smem;
        uint8_t* xs8  = (uint8_t*)(smem + 2 * BUFB);

        int b  = blockIdx.x / NCH;
        int n0 = (blockIdx.x % NCH) * CH;

        for (int i = t; i < 2 * FW; i += NTHR) {
            int buf = i / FW, xx = i % FW;
            ((float*)(bufs + buf * BUFB + FW * ROWB))[xx] = 0.f;   // pad row
        }
        for (int i = t; i < CH * FH; i += NTHR) {
            int nl = i / FH, yy = i % FH;
            int n  = n0 + nl;
            int xc = FW;
            if (n < NANCH) {
                xc = cut_xs[(size_t)n * FH + yy];
                if (invalid[(size_t)n * FH + yy]) xc = FW;
            }
            int grp = nl / ACCN, j = nl % ACCN;
            xs8[yy * XSROW + grp * 32 + j] = (uint8_t)xc;
        }

        const char* Ab = (const char*)(g_A + (size_t)b * FH * FW * KPAD);

        {
            uint32_t sdst = (uint32_t)__cvta_generic_to_shared(bufs);
            for (int i = t; i < FW * KPAD / 4; i += NTHR)
                cpa16(sdst + i * 16, Ab + i * 16);
            cpa_commit();
        }

        int grp = t / 38, kp = t % 38;
        bool active = (grp < GRPS);
        uint32_t xsoff = grp * 32;

        ull acc[ACCN];
        #pragma unroll
        for (int j = 0; j < ACCN; ++j) acc[j] = 0;

        #pragma unroll 1
        for (int y = 0; y < FH; ++y) {
            int cur = y & 1;
            __syncthreads();
            if (y + 1 < FH) {
                uint32_t sdst = (uint32_t)__cvta_generic_to_shared(bufs + (1 - cur) * BUFB);
                const char* src = Ab + (size_t)(y + 1) * FW * KPAD * 4;
                for (int i = t; i < FW * KPAD / 4; i += NTHR)
                    cpa16(sdst + i * 16, src + i * 16);
                cpa_commit();
                cpa_wait<1>();
            } else {
                cpa_wait<0>();
            }
            __syncthreads();

            if (active) {
                const char* A_s = bufs + cur * BUFB + kp * 8;
                const uint4* xw = (const uint4*)(xs8 + y * XSROW + xsoff);
                uint4 u0 = xw[0];
                uint4 u1 = xw[1];
                uint32_t uw[8] = {u0.x, u0.y, u0.z, u0.w, u1.x, u1.y, u1.z, u1.w};
                #pragma unroll
                for (int j = 0; j < ACCN; ++j) {
                    uint32_t c = (uw[j >> 2] >> ((j & 3) * 8)) & 0xFFu;
                    ull v = *(const ull*)(A_s + c * ROWB);
                    acc[j] = add2(acc[j], v);
                }
            }
        }

        if (active) {
            int k = 2 * kp;
            float b0 = (kp == 0) ? cls_b[0] : reg_b[k - 2];
            float b1 = (kp == 0) ? cls_b[1] : ((kp < 37) ? reg_b[k - 1] : 0.f);

            #pragma unroll 4
            for (int j = 0; j < ACCN; ++j) {
                int n = n0 + grp * ACCN + j;
                if (n >= NANCH) break;
                float* o = out + (size_t)(b * NANCH + n) * OUTW;
                const float* an = anchors + (size_t)n * OUTW;
                float lo = __uint_as_float((uint32_t)(acc[j] & 0xFFFFFFFFull));
                float hi = __uint_as_float((uint32_t)(acc[j] >> 32));
                if (kp == 0) {
                    o[0] = lo + b0;
                    o[1] = hi + b1;
                    o[2] = an[2];
                    o[3] = an[3];
                } else if (kp < 37) {
                    o[k + 2] = lo + b0 + an[k + 2];
                    o[k + 3] = hi + b1 + an[k + 3];
                } else {   // kp == 37: k=74 valid, k=75 is padding
                    o[76] = lo + b0 + an[76];
                }
            }
        }
    }
}

// ---------------------------------------------------------------------------
extern "C" void kernel_launch(void* const* d_in, const int* in_sizes, int n_in,
                              void* d_out, int out_size) {
    const float*   x        = (const float*)d_in[0];
    const float*   conv_w   = (const float*)d_in[1];
    const float*   conv_b   = (const float*)d_in[2];
    const float*   cls_w    = (const float*)d_in[3];
    const float*   cls_b    = (const float*)d_in[4];
    const float*   reg_w    = (const float*)d_in[5];
    const float*   reg_b    = (const float*)d_in[6];
    const float*   anchors  = (const float*)d_in[7];
    const int*     cut_xs   = (const int*)d_in[8];
    const uint8_t* invalid  = (const uint8_t*)d_in[9];
    float* out = (float*)d_out;

    // Idempotent, capture-legal.
    cudaFuncSetAttribute(fused_kernel,
                         cudaFuncAttributeMaxDynamicSharedMemorySize, SMEM_DYN);

    fused_kernel<<<NBLK, NTHR, SMEM_DYN>>>(x, conv_w, conv_b, cls_w, cls_b,
                                           reg_w, reg_b, anchors, cut_xs,
                                           invalid, out);
}

// round 14
// speedup vs baseline: 1.0810x; 1.0678x over previous
#include <cuda_runtime.h>
#include <stdint.h>

#define BATCH 16
#define CIN   64
#define CF    64
#define FH    45
#define FW    80
#define NANCH 2784
#define KOUT  75
#define KPAD  80    // padded K (cols 75..79 are zero)
#define OUTW  77

typedef unsigned long long ull;

// ---------------------------------------------------------------------------
// Scratch (static __device__ — allocation-free)
// ---------------------------------------------------------------------------
__device__ float g_W2[FH * CIN * KPAD];          // [y][cin][k]
__device__ float g_cb[FH * KPAD];                // [y][k]
__device__ float g_A[BATCH * FH * FW * KPAD];    // [b][y][x][k]

// ---------------------------------------------------------------------------
// f32x2 packed-math helpers (sm_103a)
// ---------------------------------------------------------------------------
__device__ __forceinline__ ull ffma2(ull a, ull b, ull c) {
    ull d;
    asm("fma.rn.f32x2 %0, %1, %2, %3;" : "=l"(d) : "l"(a), "l"(b), "l"(c));
    return d;
}
__device__ __forceinline__ ull add2(ull a, ull b) {
    ull r;
    asm("add.rn.f32x2 %0, %1, %2;" : "=l"(r) : "l"(a), "l"(b));
    return r;
}
__device__ __forceinline__ ull pk2(float x) {
    ull r;
    asm("mov.b64 %0, {%1, %1};" : "=l"(r) : "f"(x));
    return r;
}
__device__ __forceinline__ void cpa16(uint32_t s, const void* g) {
    asm volatile("cp.async.ca.shared.global [%0], [%1], 16;" :: "r"(s), "l"(g));
}
__device__ __forceinline__ void cpa_commit() {
    asm volatile("cp.async.commit_group;");
}
template <int N>
__device__ __forceinline__ void cpa_wait() {
    asm volatile("cp.async.wait_group %0;" :: "n"(N));
}

// ---------------------------------------------------------------------------
// K1 (prep): one output per thread, direct __ldg. High occupancy.
// ---------------------------------------------------------------------------
__global__ void __launch_bounds__(256) prep_kernel(
    const float* __restrict__ conv_w, const float* __restrict__ conv_b,
    const float* __restrict__ cls_w,  const float* __restrict__ reg_w)
{
    const int TOT = FH * 65 * KPAD;   // 234000
    int o = blockIdx.x * 256 + threadIdx.x;
    if (o >= TOT) return;
    int k  = o % KPAD;
    int r  = o / KPAD;
    int cx = r % 65;
    int y  = r / 65;
    float acc = 0.f;
    if (k < 75) {
        const float* w;
        int stride;
        if (k < 2) { w = cls_w + y * 2 + k;        stride = FH * 2; }
        else       { w = reg_w + y * 73 + (k - 2); stride = FH * 73; }
        if (cx < CIN) {
            const float* cw = conv_w + cx;
            #pragma unroll 8
            for (int cf = 0; cf < CF; ++cf)
                acc += __ldg(cw + cf * CIN) * __ldg(w + cf * stride);
        } else {
            #pragma unroll 8
            for (int cf = 0; cf < CF; ++cf)
                acc += __ldg(conv_b + cf) * __ldg(w + cf * stride);
        }
    }
    if (cx < CIN) g_W2[((size_t)y * CIN + cx) * KPAD + k] = acc;
    else          g_cb[y * KPAD + k] = acc;
}

// ---------------------------------------------------------------------------
// K2 (A-GEMM, f32x2): block per (y, b). 160 threads, 5 blocks/SM (25 warps).
// Each thread owns a 5(x) x 8(k) tile.
// ---------------------------------------------------------------------------
__global__ void __launch_bounds__(160, 5) a_kernel(const float* __restrict__ x) {
    __shared__ float w_s[CIN * KPAD];   // 20.5 KB [cin][k]
    __shared__ float cb_s[KPAD];
    __shared__ float xs_s[CIN * FW];    // 20 KB   [cin][x]

    int y = blockIdx.x;
    int b = blockIdx.y;
    int t = threadIdx.x;

    for (int i4 = t; i4 < CIN * FW / 4; i4 += 160) {
        int cin = i4 / 20, xx4 = i4 % 20;
        const float4* src = (const float4*)(x + ((size_t)(b * CIN + cin) * FH + y) * FW);
        ((float4*)xs_s)[cin * 20 + xx4] = src[xx4];
    }
    {
        const float4* src = (const float4*)(g_W2 + (size_t)y * CIN * KPAD);
        for (int i4 = t; i4 < CIN * KPAD / 4; i4 += 160) ((float4*)w_s)[i4] = src[i4];
    }
    if (t < KPAD) cb_s[t] = g_cb[y * KPAD + t];
    __syncthreads();

    int xg = t / 10, kg = t % 10;
    int x0 = xg * 5, k0 = kg * 8;

    ull acc[5][4];
    {
        ulonglong2 c01 = *(const ulonglong2*)&cb_s[k0];
        ulonglong2 c23 = *(const ulonglong2*)&cb_s[k0 + 4];
        #pragma unroll
        for (int i = 0; i < 5; ++i) {
            acc[i][0] = c01.x; acc[i][1] = c01.y;
            acc[i][2] = c23.x; acc[i][3] = c23.y;
        }
    }

    #pragma unroll 4
    for (int cin = 0; cin < CIN; ++cin) {
        ulonglong2 wA = *(const ulonglong2*)&w_s[cin * KPAD + k0];
        ulonglong2 wB = *(const ulonglong2*)&w_s[cin * KPAD + k0 + 4];
        float xv[5];
        #pragma unroll
        for (int i = 0; i < 5; ++i) xv[i] = xs_s[cin * FW + x0 + i];
        #pragma unroll
        for (int i = 0; i < 5; ++i) {
            ull px = pk2(xv[i]);
            acc[i][0] = ffma2(px, wA.x, acc[i][0]);
            acc[i][1] = ffma2(px, wA.y, acc[i][1]);
            acc[i][2] = ffma2(px, wB.x, acc[i][2]);
            acc[i][3] = ffma2(px, wB.y, acc[i][3]);
        }
    }

    float* Ab = g_A + ((size_t)(b * FH + y) * FW) * KPAD;
    #pragma unroll
    for (int i = 0; i < 5; ++i) {
        ulonglong2* dst = (ulonglong2*)(Ab + (x0 + i) * KPAD + k0);
        dst[0] = make_ulonglong2(acc[i][0], acc[i][1]);
        dst[1] = make_ulonglong2(acc[i][2], acc[i][3]);
    }
}

// ---------------------------------------------------------------------------
// K3 (gather-reduce): block per (chunk of CH=156 anchors, b). 2 blocks/SM.
// 456 compute threads = 38 k-pairs x 12 anchor-groups; ACCN = 13 anchors each.
// Double-buffered cp.async staging; zeroed 81st row absorbs invalid/pad.
// ---------------------------------------------------------------------------
#define CH       156
#define NCH      18          // 18*156 = 2808 >= 2784 (last chunk partial)
#define GRPS     12
#define ACCN     13          // CH / GRPS
#define GTHREADS 480
#define ROWB     (FW * 4)                 // 320 B per x-row
#define BUFB     ((FW + 1) * ROWB)        // 81 rows = 25920 B
#define XSROW    384
#define SMEM_GATHER (2 * BUFB + FH * XSROW)   // 51840 + 17280 = 69120

__global__ void __launch_bounds__(GTHREADS, 2) gather_kernel(
    const int*     __restrict__ cut_xs,
    const uint8_t* __restrict__ invalid,
    const float*   __restrict__ anchors,
    const float*   __restrict__ cls_b,
    const float*   __restrict__ reg_b,
    float*         __restrict__ out)
{
    extern __shared__ __align__(16) char smem[];
    char*    bufs = smem;                      // 2 x 25920 B
    uint8_t* xs8  = (uint8_t*)(smem + 2 * BUFB);

    int b  = blockIdx.y;
    int n0 = blockIdx.x * CH;
    int t  = threadIdx.x;

    // Zero the pad row (row 80) of both buffers.
    for (int i = t; i < 2 * FW; i += GTHREADS) {
        int buf = i / FW, xx = i % FW;
        ((float*)(bufs + buf * BUFB + FW * ROWB))[xx] = 0.f;
    }
    // Stage per-anchor column indices (invalid/pad -> 80, the zero row).
    for (int i = t; i < CH * FH; i += GTHREADS) {
        int nl = i / FH, yy = i % FH;
        int n  = n0 + nl;
        int xc = FW;
        if (n < NANCH) {
            xc = cut_xs[(size_t)n * FH + yy];
            if (invalid[(size_t)n * FH + yy]) xc = FW;
        }
        int grp = nl / ACCN, j = nl % ACCN;
        xs8[yy * XSROW + grp * 32 + j] = (uint8_t)xc;
    }

    const char* Ab = (const char*)(g_A + (size_t)b * FH * FW * KPAD);

    // Prefetch y=0 into buffer 0.
    {
        uint32_t sdst = (uint32_t)__cvta_generic_to_shared(bufs);
        for (int i = t; i < FW * KPAD / 4; i += GTHREADS)
            cpa16(sdst + i * 16, Ab + i * 16);
        cpa_commit();
    }

    int grp = t / 38, kp = t % 38;
    bool active = (grp < GRPS);
    uint32_t xsoff = grp * 32;

    ull acc[ACCN];
    #pragma unroll
    for (int j = 0; j < ACCN; ++j) acc[j] = 0;

    #pragma unroll 1
    for (int y = 0; y < FH; ++y) {
        int cur = y & 1;
        __syncthreads();   // buf(1-cur) free; xs visible (y==0)
        if (y + 1 < FH) {
            uint32_t sdst = (uint32_t)__cvta_generic_to_shared(bufs + (1 - cur) * BUFB);
            const char* src = Ab + (size_t)(y + 1) * FW * KPAD * 4;
            for (int i = t; i < FW * KPAD / 4; i += GTHREADS)
                cpa16(sdst + i * 16, src + i * 16);
            cpa_commit();
            cpa_wait<1>();
        } else {
            cpa_wait<0>();
        }
        __syncthreads();   // buf(cur) visible

        if (active) {
            const char* A_s = bufs + cur * BUFB + kp * 8;
            uint4 u0 = *(const uint4*)(xs8 + y * XSROW + xsoff);   // 13 <= 16 idx
            uint32_t uw[4] = {u0.x, u0.y, u0.z, u0.w};
            #pragma unroll
            for (int j = 0; j < ACCN; ++j) {
                uint32_t c = (uw[j >> 2] >> ((j & 3) * 8)) & 0xFFu;
                ull v = *(const ull*)(A_s + c * ROWB);
                acc[j] = add2(acc[j], v);
            }
        }
    }

    if (!active) return;

    int k = 2 * kp;
    float b0 = (kp == 0) ? cls_b[0] : reg_b[k - 2];
    float b1 = (kp == 0) ? cls_b[1] : ((kp < 37) ? reg_b[k - 1] : 0.f);

    #pragma unroll 4
    for (int j = 0; j < ACCN; ++j) {
        int n = n0 + grp * ACCN + j;
        if (n >= NANCH) break;
        float* o = out + (size_t)(b * NANCH + n) * OUTW;
        const float* an = anchors + (size_t)n * OUTW;
        float lo = __uint_as_float((uint32_t)(acc[j] & 0xFFFFFFFFull));
        float hi = __uint_as_float((uint32_t)(acc[j] >> 32));
        if (kp == 0) {
            o[0] = lo + b0;
            o[1] = hi + b1;
            o[2] = an[2];
            o[3] = an[3];
        } else if (kp < 37) {
            o[k + 2] = lo + b0 + an[k + 2];
            o[k + 3] = hi + b1 + an[k + 3];
        } else {   // kp == 37: k=74 valid, k=75 is padding
            o[76] = lo + b0 + an[76];
        }
    }
}

// ---------------------------------------------------------------------------
extern "C" void kernel_launch(void* const* d_in, const int* in_sizes, int n_in,
                              void* d_out, int out_size) {
    const float*   x        = (const float*)d_in[0];
    const float*   conv_w   = (const float*)d_in[1];
    const float*   conv_b   = (const float*)d_in[2];
    const float*   cls_w    = (const float*)d_in[3];
    const float*   cls_b    = (const float*)d_in[4];
    const float*   reg_w    = (const float*)d_in[5];
    const float*   reg_b    = (const float*)d_in[6];
    const float*   anchors  = (const float*)d_in[7];
    const int*     cut_xs   = (const int*)d_in[8];
    const uint8_t* invalid  = (const uint8_t*)d_in[9];
    float* out = (float*)d_out;

    // Idempotent, capture-legal.
    cudaFuncSetAttribute(gather_kernel,
                         cudaFuncAttributeMaxDynamicSharedMemorySize,
                         SMEM_GATHER);

    const int TOT = FH * 65 * KPAD;
    prep_kernel<<<(TOT + 255) / 256, 256>>>(conv_w, conv_b, cls_w, reg_w);

    dim3 agrid(FH, BATCH);
    a_kernel<<<agrid, 160>>>(x);

    dim3 ggrid(NCH, BATCH);
    gather_kernel<<<ggrid, GTHREADS, SMEM_GATHER>>>(cut_xs, invalid, anchors,
                                                    cls_b, reg_b, out);
}